// round 1
// baseline (speedup 1.0000x reference)
#include <cuda_runtime.h>
#include <cuda_bf16.h>
#include <math.h>

// ---------------- problem constants ----------------
#define V_ 50257
#define D_ 384
#define T_ 300
#define B_ 16
#define H_ 16
#define DH_ 24
#define L_ 8
#define FF_ 1536
#define BT_ (B_ * T_)   // 4800

// ---------------- scratch (device globals; no allocation allowed) ---------
__device__ float g_x[BT_ * D_];          // residual stream
__device__ float g_qkv[BT_ * 3 * D_];    // fused qkv output [BT, 1152]
__device__ float g_o[BT_ * D_];          // attention output (concat heads) / final-LN xf
__device__ float g_y[BT_ * D_];          // proj / mlp2 output
__device__ float g_hid[BT_ * FF_];       // mlp hidden
__device__ float g_Bpack[D_ * 3 * D_];   // packed per-layer qkv weights [384,1152]
__device__ float g_rowloss[BT_];

// ---------------- embedding: x = tok_emb[index] + pos_emb ----------------
__global__ void embed_kernel(const int* __restrict__ index,
                             const float* __restrict__ tok_emb,
                             const float* __restrict__ pos_emb) {
    int i = blockIdx.x * blockDim.x + threadIdx.x;
    int total = BT_ * D_;
    if (i >= total) return;
    int row = i / D_;
    int d   = i % D_;
    int t   = row % T_;
    g_x[i] = tok_emb[(size_t)index[row] * D_ + d] + pos_emb[t * D_ + d];
}

// ---------------- pack Wq/Wk/Wv[l] -> [D, 3*D] (col = which*D + h*DH + e) --
__global__ void pack_qkv_kernel(const float* __restrict__ Wq,
                                const float* __restrict__ Wk,
                                const float* __restrict__ Wv, int l) {
    int idx = blockIdx.x * blockDim.x + threadIdx.x;
    const int total = D_ * 3 * D_;
    if (idx >= total) return;
    int d = idx / (3 * D_);
    int c = idx % (3 * D_);
    int which = c / D_;
    int j = c % D_;
    int h = j / DH_;
    int e = j % DH_;
    const float* W = (which == 0) ? Wq : (which == 1) ? Wk : Wv;
    // W layout: [L, H, D, DH]
    g_Bpack[idx] = W[(((size_t)l * H_ + h) * D_ + d) * DH_ + e];
}

// ---------------- SGEMM: C[M,N] = A[M,K] @ B[K,N] (+bias, optional relu) --
// BM=BN=128, BK=8, 256 threads, 8x8 micro-tile. K must be a multiple of 8.
__global__ __launch_bounds__(256)
void sgemm_kernel(const float* __restrict__ A, const float* __restrict__ B,
                  const float* __restrict__ bias, float* __restrict__ C,
                  int M, int N, int K, int relu) {
    __shared__ float As[8][128];
    __shared__ float Bs[8][128];
    int tid = threadIdx.x;
    int bm = blockIdx.y * 128;
    int bn = blockIdx.x * 128;
    int tx = tid % 16;      // col group
    int ty = tid / 16;      // row group

    float acc[8][8];
#pragma unroll
    for (int i = 0; i < 8; i++)
#pragma unroll
        for (int j = 0; j < 8; j++) acc[i][j] = 0.0f;

    int a_row  = tid >> 1;           // 0..127
    int a_col4 = (tid & 1) * 4;      // 0 or 4
    int b_row  = tid >> 5;           // 0..7
    int b_col  = (tid & 31) * 4;     // 0..124

    for (int k0 = 0; k0 < K; k0 += 8) {
        // A tile (float4: K is a multiple of 4 here, rows aligned)
        float4 av = make_float4(0.f, 0.f, 0.f, 0.f);
        if (bm + a_row < M)
            av = *reinterpret_cast<const float4*>(&A[(size_t)(bm + a_row) * K + k0 + a_col4]);
        As[a_col4 + 0][a_row] = av.x;
        As[a_col4 + 1][a_row] = av.y;
        As[a_col4 + 2][a_row] = av.z;
        As[a_col4 + 3][a_row] = av.w;
        // B tile (scalar loads: N may be odd, e.g. 50257)
#pragma unroll
        for (int u = 0; u < 4; u++) {
            int col = bn + b_col + u;
            Bs[b_row][b_col + u] = (col < N) ? B[(size_t)(k0 + b_row) * N + col] : 0.0f;
        }
        __syncthreads();
#pragma unroll
        for (int kk = 0; kk < 8; kk++) {
            float a[8], bb[8];
#pragma unroll
            for (int i = 0; i < 8; i++) a[i] = As[kk][ty * 8 + i];
#pragma unroll
            for (int j = 0; j < 8; j++) bb[j] = Bs[kk][tx * 8 + j];
#pragma unroll
            for (int i = 0; i < 8; i++)
#pragma unroll
                for (int j = 0; j < 8; j++) acc[i][j] += a[i] * bb[j];
        }
        __syncthreads();
    }

#pragma unroll
    for (int i = 0; i < 8; i++) {
        int row = bm + ty * 8 + i;
        if (row >= M) continue;
#pragma unroll
        for (int j = 0; j < 8; j++) {
            int col = bn + tx * 8 + j;
            if (col >= N) continue;
            float v = acc[i][j];
            if (bias) v += bias[col];
            if (relu) v = fmaxf(v, 0.0f);
            C[(size_t)row * N + col] = v;
        }
    }
}

// ---------------- attention: one block per (tq, b*h) ----------------
__global__ __launch_bounds__(128)
void attn_kernel() {
    int tq = blockIdx.x;
    int bh = blockIdx.y;
    int b = bh / H_;
    int h = bh % H_;
    int tid = threadIdx.x;

    __shared__ float sc[T_];     // scores / probs
    __shared__ float red[128];
    __shared__ float qs[DH_];
    __shared__ float oacc[128];

    const int base = (b * T_) * (3 * D_);
    if (tid < DH_) qs[tid] = g_qkv[(size_t)(b * T_ + tq) * (3 * D_) + h * DH_ + tid];
    __syncthreads();

    const float scale = rsqrtf((float)DH_);

    float lmax = -INFINITY;
    for (int ts = tid; ts <= tq; ts += 128) {
        const float* kp = &g_qkv[(size_t)base + (size_t)ts * (3 * D_) + D_ + h * DH_];
        float s = 0.0f;
#pragma unroll
        for (int e = 0; e < DH_; e++) s += qs[e] * kp[e];
        s *= scale;
        sc[ts] = s;
        lmax = fmaxf(lmax, s);
    }
    red[tid] = lmax;
    __syncthreads();
    for (int o = 64; o > 0; o >>= 1) {
        if (tid < o) red[tid] = fmaxf(red[tid], red[tid + o]);
        __syncthreads();
    }
    float m = red[0];
    __syncthreads();

    float lsum = 0.0f;
    for (int ts = tid; ts <= tq; ts += 128) {
        float p = __expf(sc[ts] - m);
        sc[ts] = p;
        lsum += p;
    }
    red[tid] = lsum;
    __syncthreads();
    for (int o = 64; o > 0; o >>= 1) {
        if (tid < o) red[tid] += red[tid + o];
        __syncthreads();
    }
    float inv = 1.0f / red[0];
    __syncthreads();

    // P@V: 120 threads = 24 dims x 5 row-groups
    float acc = 0.0f;
    if (tid < 120) {
        int e = tid % DH_;
        int r = tid / DH_;
        for (int ts = r; ts <= tq; ts += 5) {
            acc += sc[ts] * g_qkv[(size_t)base + (size_t)ts * (3 * D_) + 2 * D_ + h * DH_ + e];
        }
    }
    oacc[tid] = (tid < 120) ? acc : 0.0f;
    __syncthreads();
    if (tid < DH_) {
        float o = (oacc[tid] + oacc[tid + 24] + oacc[tid + 48] +
                   oacc[tid + 72] + oacc[tid + 96]) * inv;
        g_o[(size_t)(b * T_ + tq) * D_ + h * DH_ + tid] = o;
    }
}

// ---------------- fused residual-add + LayerNorm ----------------
// out = LN(x + y) with gamma/beta. y==nullptr => plain LN(x).
__global__ __launch_bounds__(128)
void add_ln_kernel(const float* __restrict__ x, const float* __restrict__ y,
                   const float* __restrict__ g, const float* __restrict__ bta,
                   float* __restrict__ out) {
    int row = blockIdx.x;
    int tid = threadIdx.x;
    __shared__ float buf[D_];
    __shared__ float red[128];

    float s = 0.0f;
#pragma unroll
    for (int i = 0; i < D_ / 128; i++) {
        int d = tid + i * 128;
        float t = x[(size_t)row * D_ + d];
        if (y) t += y[(size_t)row * D_ + d];
        buf[d] = t;
        s += t;
    }
    red[tid] = s;
    __syncthreads();
    for (int o = 64; o > 0; o >>= 1) {
        if (tid < o) red[tid] += red[tid + o];
        __syncthreads();
    }
    float mean = red[0] / D_;
    __syncthreads();

    float s2 = 0.0f;
#pragma unroll
    for (int i = 0; i < D_ / 128; i++) {
        int d = tid + i * 128;
        float t = buf[d] - mean;
        s2 += t * t;
    }
    red[tid] = s2;
    __syncthreads();
    for (int o = 64; o > 0; o >>= 1) {
        if (tid < o) red[tid] += red[tid + o];
        __syncthreads();
    }
    float rstd = rsqrtf(red[0] / D_ + 1e-5f);
    __syncthreads();

#pragma unroll
    for (int i = 0; i < D_ / 128; i++) {
        int d = tid + i * 128;
        out[(size_t)row * D_ + d] = (buf[d] - mean) * rstd * g[d] + bta[d];
    }
}

// ---------------- per-row loss from materialized logits ----------------
__global__ __launch_bounds__(256)
void row_loss_kernel(const float* __restrict__ logits, const int* __restrict__ targets) {
    int row = blockIdx.x;
    int tid = threadIdx.x;
    int tgt = targets[row];
    const float* lr = logits + (size_t)row * V_;

    __shared__ float sm[256], ss[256];
    __shared__ float szt;

    float m = -INFINITY, s = 0.0f, zt = 0.0f;
    for (int j = tid; j < V_; j += 256) {
        float z = lr[j];
        if (j == tgt) zt = z;
        float nm = fmaxf(m, z);
        s = s * __expf(m - nm) + __expf(z - nm);
        m = nm;
    }
    if ((tgt & 255) == tid) szt = zt;
    sm[tid] = m; ss[tid] = s;
    __syncthreads();
    for (int o = 128; o > 0; o >>= 1) {
        if (tid < o) {
            float m2 = sm[tid + o], s2 = ss[tid + o];
            float nm = fmaxf(sm[tid], m2);
            ss[tid] = ss[tid] * __expf(sm[tid] - nm) + s2 * __expf(m2 - nm);
            sm[tid] = nm;
        }
        __syncthreads();
    }
    if (tid == 0) g_rowloss[row] = (sm[0] + logf(ss[0])) - szt;
}

// ---------------- fallback: fused logits+loss (no materialized logits) ----
__global__ __launch_bounds__(256)
void loss_direct_kernel(const float* __restrict__ xf, const float* __restrict__ Wout,
                        const float* __restrict__ bout, const int* __restrict__ targets) {
    int row = blockIdx.x;
    int tid = threadIdx.x;
    int tgt = targets[row];
    __shared__ float xs[D_];
    __shared__ float sm[256], ss[256];
    __shared__ float szt;
    for (int i = tid; i < D_; i += 256) xs[i] = xf[(size_t)row * D_ + i];
    __syncthreads();

    float m = -INFINITY, s = 0.0f, zt = 0.0f;
    for (int j = tid; j < V_; j += 256) {
        float z = bout[j];
        for (int k = 0; k < D_; k++) z += xs[k] * Wout[(size_t)k * V_ + j];
        if (j == tgt) zt = z;
        float nm = fmaxf(m, z);
        s = s * __expf(m - nm) + __expf(z - nm);
        m = nm;
    }
    if ((tgt & 255) == tid) szt = zt;
    sm[tid] = m; ss[tid] = s;
    __syncthreads();
    for (int o = 128; o > 0; o >>= 1) {
        if (tid < o) {
            float m2 = sm[tid + o], s2 = ss[tid + o];
            float nm = fmaxf(sm[tid], m2);
            ss[tid] = ss[tid] * __expf(sm[tid] - nm) + s2 * __expf(m2 - nm);
            sm[tid] = nm;
        }
        __syncthreads();
    }
    if (tid == 0) g_rowloss[row] = (sm[0] + logf(ss[0])) - szt;
}

__global__ __launch_bounds__(256)
void reduce_loss_kernel(float* __restrict__ out) {
    __shared__ float red[256];
    int tid = threadIdx.x;
    float s = 0.0f;
    for (int i = tid; i < BT_; i += 256) s += g_rowloss[i];
    red[tid] = s;
    __syncthreads();
    for (int o = 128; o > 0; o >>= 1) {
        if (tid < o) red[tid] += red[tid + o];
        __syncthreads();
    }
    if (tid == 0) out[0] = red[0] / (float)BT_;
}

// ---------------- host orchestration ----------------
static inline void run_sgemm(const float* A, const float* B, const float* bias,
                             float* C, int M, int N, int K, int relu) {
    dim3 grid((N + 127) / 128, (M + 127) / 128);
    sgemm_kernel<<<grid, 256>>>(A, B, bias, C, M, N, K, relu);
}

extern "C" void kernel_launch(void* const* d_in, const int* in_sizes, int n_in,
                              void* d_out, int out_size) {
    // metadata order
    const int*   index   = (const int*)  d_in[0];
    const int*   targets = (const int*)  d_in[1];
    const float* tok_emb = (const float*)d_in[2];
    const float* pos_emb = (const float*)d_in[3];
    const float* Wq      = (const float*)d_in[4];
    const float* Wk      = (const float*)d_in[5];
    const float* Wv      = (const float*)d_in[6];
    const float* Wo      = (const float*)d_in[7];
    const float* bo      = (const float*)d_in[8];
    const float* W1      = (const float*)d_in[9];
    const float* b1      = (const float*)d_in[10];
    const float* b2w     = (const float*)d_in[11]; // W2
    const float* b2      = (const float*)d_in[12];
    const float* ln1_g   = (const float*)d_in[13];
    const float* ln1_b   = (const float*)d_in[14];
    const float* ln2_g   = (const float*)d_in[15];
    const float* ln2_b   = (const float*)d_in[16];
    const float* lnf_g   = (const float*)d_in[17];
    const float* lnf_b   = (const float*)d_in[18];
    const float* Wout    = (const float*)d_in[19];
    const float* bout    = (const float*)d_in[20];
    float* out = (float*)d_out;

    float *x, *qkv, *o, *y, *hid, *bpack;
    cudaGetSymbolAddress((void**)&x,     g_x);
    cudaGetSymbolAddress((void**)&qkv,   g_qkv);
    cudaGetSymbolAddress((void**)&o,     g_o);
    cudaGetSymbolAddress((void**)&y,     g_y);
    cudaGetSymbolAddress((void**)&hid,   g_hid);
    cudaGetSymbolAddress((void**)&bpack, g_Bpack);

    // 1. embedding
    {
        int total = BT_ * D_;
        embed_kernel<<<(total + 255) / 256, 256>>>(index, tok_emb, pos_emb);
    }

    // 2. transformer layers
    for (int l = 0; l < L_; l++) {
        // pack qkv weights for this layer
        {
            int total = D_ * 3 * D_;
            pack_qkv_kernel<<<(total + 255) / 256, 256>>>(Wq, Wk, Wv, l);
        }
        // qkv = x @ Bpack  [4800,384]x[384,1152]
        run_sgemm(x, bpack, nullptr, qkv, BT_, 3 * D_, D_, 0);
        // attention -> g_o [4800,384] (concat heads)
        {
            dim3 grid(T_, B_ * H_);
            attn_kernel<<<grid, 128>>>();
        }
        // y = o @ Wo[l] + bo[l]
        run_sgemm(o, Wo + (size_t)l * D_ * D_, bo + (size_t)l * D_, y, BT_, D_, D_, 0);
        // x = LN(x + y)
        add_ln_kernel<<<BT_, 128>>>(x, y, ln1_g + (size_t)l * D_, ln1_b + (size_t)l * D_, x);
        // hid = relu(x @ W1[l] + b1[l])
        run_sgemm(x, W1 + (size_t)l * D_ * FF_, b1 + (size_t)l * FF_, hid, BT_, FF_, D_, 1);
        // y = hid @ W2[l] + b2[l]
        run_sgemm(hid, b2w + (size_t)l * FF_ * D_, b2 + (size_t)l * D_, y, BT_, D_, FF_, 0);
        // x = LN(x + y)
        add_ln_kernel<<<BT_, 128>>>(x, y, ln2_g + (size_t)l * D_, ln2_b + (size_t)l * D_, x);
    }

    // 3. final LN -> xf in g_o
    add_ln_kernel<<<BT_, 128>>>(x, nullptr, lnf_g, lnf_b, o);

    const long long LOGITS = (long long)BT_ * V_;
    if ((long long)out_size >= LOGITS) {
        // 4. logits = xf @ Wout + bout  -> d_out
        run_sgemm(o, Wout, bout, out, BT_, V_, D_, 0);
        if ((long long)out_size > LOGITS) {
            // 5. loss
            row_loss_kernel<<<BT_, 256>>>(out, targets);
            reduce_loss_kernel<<<1, 256>>>(out + LOGITS);
        }
    } else {
        // fallback: out too small for logits — compute loss only into out[0]
        loss_direct_kernel<<<BT_, 256>>>(o, Wout, bout, targets);
        reduce_loss_kernel<<<1, 256>>>(out);
    }
}

// round 2
// speedup vs baseline: 1.4570x; 1.4570x over previous
#include <cuda_runtime.h>
#include <cuda_bf16.h>
#include <math.h>
#include <stdint.h>

// ---------------- problem constants ----------------
#define V_ 50257
#define D_ 384
#define T_ 300
#define B_ 16
#define H_ 16
#define DH_ 24
#define L_ 8
#define FF_ 1536
#define BT_ (B_ * T_)   // 4800

// ---------------- scratch (device globals; no allocation allowed) ---------
__device__ float g_x[BT_ * D_];          // residual stream
__device__ float g_qkv[BT_ * 3 * D_];    // fused qkv output [BT, 1152]
__device__ float g_o[BT_ * D_];          // attention out / final-LN xf
__device__ float g_y[BT_ * D_];          // proj / mlp2 output
__device__ float g_hid[BT_ * FF_];       // mlp hidden
__device__ float g_Bpack[D_ * 3 * D_];   // packed per-layer qkv weights [384,1152]
__device__ float g_rowloss[BT_];

// ---------------- embedding ----------------
__global__ void embed_kernel(const int* __restrict__ index,
                             const float* __restrict__ tok_emb,
                             const float* __restrict__ pos_emb) {
    int i = blockIdx.x * blockDim.x + threadIdx.x;
    int total = BT_ * D_;
    if (i >= total) return;
    int row = i / D_;
    int d   = i % D_;
    int t   = row % T_;
    g_x[i] = tok_emb[(size_t)index[row] * D_ + d] + pos_emb[t * D_ + d];
}

// ---------------- pack Wq/Wk/Wv[l] -> [D, 3*D] ----------------
__global__ void pack_qkv_kernel(const float* __restrict__ Wq,
                                const float* __restrict__ Wk,
                                const float* __restrict__ Wv, int l) {
    int idx = blockIdx.x * blockDim.x + threadIdx.x;
    const int total = D_ * 3 * D_;
    if (idx >= total) return;
    int d = idx / (3 * D_);
    int c = idx % (3 * D_);
    int which = c / D_;
    int j = c % D_;
    int h = j / DH_;
    int e = j % DH_;
    const float* W = (which == 0) ? Wq : (which == 1) ? Wk : Wv;
    g_Bpack[idx] = W[(((size_t)l * H_ + h) * D_ + d) * DH_ + e];
}

// ==================== bf16x3 tensor-core GEMM ====================
// C[M,N] = A[M,K] @ B[K,N] (+bias, optional relu), fp32 in/out.
// Split each fp32 into hi+lo bf16; D ~= Ah*Bh + Ah*Bl + Al*Bh (fp32 acc).
// Block tile 128x128x32, 8 warps of 64x32, mma.sync m16n8k16.

#define BM 128
#define BN 128
#define BKT 32

__device__ __forceinline__ void bf16_split(float x, __nv_bfloat16& h, __nv_bfloat16& l) {
    h = __float2bfloat16_rn(x);
    l = __float2bfloat16_rn(x - __bfloat162float(h));
}

__device__ __forceinline__ uint32_t smem_u32(const void* p) {
    return (uint32_t)__cvta_generic_to_shared(p);
}

__device__ __forceinline__ void ldm_x4(uint32_t* r, uint32_t addr) {
    asm volatile("ldmatrix.sync.aligned.m8n8.x4.shared.b16 {%0,%1,%2,%3}, [%4];"
                 : "=r"(r[0]), "=r"(r[1]), "=r"(r[2]), "=r"(r[3]) : "r"(addr));
}
__device__ __forceinline__ void ldm_x2_t(uint32_t* r, uint32_t addr) {
    asm volatile("ldmatrix.sync.aligned.m8n8.x2.trans.shared.b16 {%0,%1}, [%2];"
                 : "=r"(r[0]), "=r"(r[1]) : "r"(addr));
}
__device__ __forceinline__ void mma_bf16(float* d, const uint32_t* a, const uint32_t* b) {
    asm volatile("mma.sync.aligned.m16n8k16.row.col.f32.bf16.bf16.f32 "
                 "{%0,%1,%2,%3},{%4,%5,%6,%7},{%8,%9},{%0,%1,%2,%3};"
                 : "+f"(d[0]), "+f"(d[1]), "+f"(d[2]), "+f"(d[3])
                 : "r"(a[0]), "r"(a[1]), "r"(a[2]), "r"(a[3]), "r"(b[0]), "r"(b[1]));
}

#define A_PAD 40    // 40 bf16 = 80B row stride (20 words): conflict-free ldmatrix
#define B_PAD 136   // 136 bf16 = 272B row stride (68 words): conflict-free ldmatrix

__global__ __launch_bounds__(256)
void gemm_bf16x3_kernel(const float* __restrict__ A, const float* __restrict__ B,
                        const float* __restrict__ bias, float* __restrict__ C,
                        int M, int N, int K, int relu) {
    __shared__ __nv_bfloat16 Ah[BM][A_PAD];
    __shared__ __nv_bfloat16 Al[BM][A_PAD];
    __shared__ __nv_bfloat16 Bh[BKT][B_PAD];
    __shared__ __nv_bfloat16 Bl[BKT][B_PAD];

    const int tid = threadIdx.x;
    const int warp = tid >> 5;
    const int lane = tid & 31;
    const int wm = (warp >> 2) * 64;   // warp row offset in tile
    const int wn = (warp & 3) * 32;    // warp col offset in tile
    const int bm = blockIdx.y * BM;
    const int bn = blockIdx.x * BN;

    float acc[4][4][4];
#pragma unroll
    for (int i = 0; i < 4; i++)
#pragma unroll
        for (int j = 0; j < 4; j++)
#pragma unroll
            for (int f = 0; f < 4; f++) acc[i][j][f] = 0.0f;

    // ldmatrix source coords (per lane)
    const int a_row = (lane & 7) + ((lane >> 3) & 1) * 8;   // 0..15
    const int a_k8  = (lane >> 4) * 8;                      // 0 or 8
    const int b_row = lane & 15;                            // 0..15 (lanes>=16 ignored)

    for (int k0 = 0; k0 < K; k0 += BKT) {
        // ---- load A tile (128x32 fp32 -> split bf16), float4 x4 per thread
#pragma unroll
        for (int i = 0; i < 4; i++) {
            int e = tid + i * 256;          // float4 index 0..1023
            int r = e >> 3;                 // 0..127
            int c = (e & 7) * 4;            // 0..28
            float4 v = make_float4(0.f, 0.f, 0.f, 0.f);
            if (bm + r < M)
                v = *reinterpret_cast<const float4*>(&A[(size_t)(bm + r) * K + k0 + c]);
            __nv_bfloat16 h, l;
            bf16_split(v.x, h, l); Ah[r][c + 0] = h; Al[r][c + 0] = l;
            bf16_split(v.y, h, l); Ah[r][c + 1] = h; Al[r][c + 1] = l;
            bf16_split(v.z, h, l); Ah[r][c + 2] = h; Al[r][c + 2] = l;
            bf16_split(v.w, h, l); Ah[r][c + 3] = h; Al[r][c + 3] = l;
        }
        // ---- load B tile (32x128 fp32 -> split bf16), scalar x16 per thread
#pragma unroll
        for (int i = 0; i < 16; i++) {
            int e = tid + i * 256;          // 0..4095
            int r = e >> 7;                 // 0..31
            int c = e & 127;                // 0..127
            float v = 0.0f;
            if (bn + c < N) v = B[(size_t)(k0 + r) * N + bn + c];
            __nv_bfloat16 h, l;
            bf16_split(v, h, l);
            Bh[r][c] = h; Bl[r][c] = l;
        }
        __syncthreads();

#pragma unroll
        for (int ks = 0; ks < 2; ks++) {
            const int kk = ks * 16;
            uint32_t ah[4][4], al[4][4], bh[4][2], bl[4][2];
#pragma unroll
            for (int mt = 0; mt < 4; mt++) {
                int row = wm + mt * 16 + a_row;
                ldm_x4(ah[mt], smem_u32(&Ah[row][kk + a_k8]));
                ldm_x4(al[mt], smem_u32(&Al[row][kk + a_k8]));
            }
#pragma unroll
            for (int nt = 0; nt < 4; nt++) {
                int col = wn + nt * 8;
                ldm_x2_t(bh[nt], smem_u32(&Bh[kk + b_row][col]));
                ldm_x2_t(bl[nt], smem_u32(&Bl[kk + b_row][col]));
            }
#pragma unroll
            for (int mt = 0; mt < 4; mt++)
#pragma unroll
                for (int nt = 0; nt < 4; nt++) {
                    mma_bf16(acc[mt][nt], ah[mt], bh[nt]);
                    mma_bf16(acc[mt][nt], ah[mt], bl[nt]);
                    mma_bf16(acc[mt][nt], al[mt], bh[nt]);
                }
        }
        __syncthreads();
    }

    // ---- epilogue
    const int gid = lane >> 2;       // group id 0..7
    const int tig = lane & 3;        // thread in group
#pragma unroll
    for (int mt = 0; mt < 4; mt++) {
#pragma unroll
        for (int nt = 0; nt < 4; nt++) {
            int row0 = bm + wm + mt * 16 + gid;
            int col0 = bn + wn + nt * 8 + tig * 2;
#pragma unroll
            for (int f = 0; f < 4; f++) {
                int row = row0 + (f >> 1) * 8;
                int col = col0 + (f & 1);
                if (row < M && col < N) {
                    float v = acc[mt][nt][f];
                    if (bias) v += bias[col];
                    if (relu) v = fmaxf(v, 0.0f);
                    C[(size_t)row * N + col] = v;
                }
            }
        }
    }
}

// ---------------- attention: one block per (tq, b*h) ----------------
__global__ __launch_bounds__(128)
void attn_kernel() {
    int tq = blockIdx.x;
    int bh = blockIdx.y;
    int b = bh / H_;
    int h = bh % H_;
    int tid = threadIdx.x;

    __shared__ float sc[T_];
    __shared__ float red[128];
    __shared__ float qs[DH_];
    __shared__ float oacc[128];

    const int base = (b * T_) * (3 * D_);
    if (tid < DH_) qs[tid] = g_qkv[(size_t)(b * T_ + tq) * (3 * D_) + h * DH_ + tid];
    __syncthreads();

    const float scale = rsqrtf((float)DH_);

    float lmax = -INFINITY;
    for (int ts = tid; ts <= tq; ts += 128) {
        const float* kp = &g_qkv[(size_t)base + (size_t)ts * (3 * D_) + D_ + h * DH_];
        float s = 0.0f;
#pragma unroll
        for (int e = 0; e < DH_; e++) s += qs[e] * kp[e];
        s *= scale;
        sc[ts] = s;
        lmax = fmaxf(lmax, s);
    }
    red[tid] = lmax;
    __syncthreads();
    for (int o = 64; o > 0; o >>= 1) {
        if (tid < o) red[tid] = fmaxf(red[tid], red[tid + o]);
        __syncthreads();
    }
    float m = red[0];
    __syncthreads();

    float lsum = 0.0f;
    for (int ts = tid; ts <= tq; ts += 128) {
        float p = __expf(sc[ts] - m);
        sc[ts] = p;
        lsum += p;
    }
    red[tid] = lsum;
    __syncthreads();
    for (int o = 64; o > 0; o >>= 1) {
        if (tid < o) red[tid] += red[tid + o];
        __syncthreads();
    }
    float inv = 1.0f / red[0];
    __syncthreads();

    float acc = 0.0f;
    if (tid < 120) {
        int e = tid % DH_;
        int r = tid / DH_;
        for (int ts = r; ts <= tq; ts += 5) {
            acc += sc[ts] * g_qkv[(size_t)base + (size_t)ts * (3 * D_) + 2 * D_ + h * DH_ + e];
        }
    }
    oacc[tid] = (tid < 120) ? acc : 0.0f;
    __syncthreads();
    if (tid < DH_) {
        float o = (oacc[tid] + oacc[tid + 24] + oacc[tid + 48] +
                   oacc[tid + 72] + oacc[tid + 96]) * inv;
        g_o[(size_t)(b * T_ + tq) * D_ + h * DH_ + tid] = o;
    }
}

// ---------------- fused residual-add + LayerNorm ----------------
__global__ __launch_bounds__(128)
void add_ln_kernel(const float* __restrict__ x, const float* __restrict__ y,
                   const float* __restrict__ g, const float* __restrict__ bta,
                   float* __restrict__ out) {
    int row = blockIdx.x;
    int tid = threadIdx.x;
    __shared__ float buf[D_];
    __shared__ float red[128];

    float s = 0.0f;
#pragma unroll
    for (int i = 0; i < D_ / 128; i++) {
        int d = tid + i * 128;
        float t = x[(size_t)row * D_ + d];
        if (y) t += y[(size_t)row * D_ + d];
        buf[d] = t;
        s += t;
    }
    red[tid] = s;
    __syncthreads();
    for (int o = 64; o > 0; o >>= 1) {
        if (tid < o) red[tid] += red[tid + o];
        __syncthreads();
    }
    float mean = red[0] / D_;
    __syncthreads();

    float s2 = 0.0f;
#pragma unroll
    for (int i = 0; i < D_ / 128; i++) {
        int d = tid + i * 128;
        float t = buf[d] - mean;
        s2 += t * t;
    }
    red[tid] = s2;
    __syncthreads();
    for (int o = 64; o > 0; o >>= 1) {
        if (tid < o) red[tid] += red[tid + o];
        __syncthreads();
    }
    float rstd = rsqrtf(red[0] / D_ + 1e-5f);
    __syncthreads();

#pragma unroll
    for (int i = 0; i < D_ / 128; i++) {
        int d = tid + i * 128;
        out[(size_t)row * D_ + d] = (buf[d] - mean) * rstd * g[d] + bta[d];
    }
}

// ---------------- per-row loss from materialized logits ----------------
__global__ __launch_bounds__(256)
void row_loss_kernel(const float* __restrict__ logits, const int* __restrict__ targets) {
    int row = blockIdx.x;
    int tid = threadIdx.x;
    int tgt = targets[row];
    const float* lr = logits + (size_t)row * V_;

    __shared__ float sm[256], ss[256];
    __shared__ float szt;

    float m = -INFINITY, s = 0.0f, zt = 0.0f;
    for (int j = tid; j < V_; j += 256) {
        float z = lr[j];
        if (j == tgt) zt = z;
        float nm = fmaxf(m, z);
        s = s * __expf(m - nm) + __expf(z - nm);
        m = nm;
    }
    if ((tgt & 255) == tid) szt = zt;
    sm[tid] = m; ss[tid] = s;
    __syncthreads();
    for (int o = 128; o > 0; o >>= 1) {
        if (tid < o) {
            float m2 = sm[tid + o], s2 = ss[tid + o];
            float nm = fmaxf(sm[tid], m2);
            ss[tid] = ss[tid] * __expf(sm[tid] - nm) + s2 * __expf(m2 - nm);
            sm[tid] = nm;
        }
        __syncthreads();
    }
    if (tid == 0) g_rowloss[row] = (sm[0] + logf(ss[0])) - szt;
}

// ---------------- fallback: fused logits+loss ----------------
__global__ __launch_bounds__(256)
void loss_direct_kernel(const float* __restrict__ xf, const float* __restrict__ Wout,
                        const float* __restrict__ bout, const int* __restrict__ targets) {
    int row = blockIdx.x;
    int tid = threadIdx.x;
    int tgt = targets[row];
    __shared__ float xs[D_];
    __shared__ float sm[256], ss[256];
    __shared__ float szt;
    for (int i = tid; i < D_; i += 256) xs[i] = xf[(size_t)row * D_ + i];
    __syncthreads();

    float m = -INFINITY, s = 0.0f, zt = 0.0f;
    for (int j = tid; j < V_; j += 256) {
        float z = bout[j];
        for (int k = 0; k < D_; k++) z += xs[k] * Wout[(size_t)k * V_ + j];
        if (j == tgt) zt = z;
        float nm = fmaxf(m, z);
        s = s * __expf(m - nm) + __expf(z - nm);
        m = nm;
    }
    if ((tgt & 255) == tid) szt = zt;
    sm[tid] = m; ss[tid] = s;
    __syncthreads();
    for (int o = 128; o > 0; o >>= 1) {
        if (tid < o) {
            float m2 = sm[tid + o], s2 = ss[tid + o];
            float nm = fmaxf(sm[tid], m2);
            ss[tid] = ss[tid] * __expf(sm[tid] - nm) + s2 * __expf(m2 - nm);
            sm[tid] = nm;
        }
        __syncthreads();
    }
    if (tid == 0) g_rowloss[row] = (sm[0] + logf(ss[0])) - szt;
}

__global__ __launch_bounds__(256)
void reduce_loss_kernel(float* __restrict__ out) {
    __shared__ float red[256];
    int tid = threadIdx.x;
    float s = 0.0f;
    for (int i = tid; i < BT_; i += 256) s += g_rowloss[i];
    red[tid] = s;
    __syncthreads();
    for (int o = 128; o > 0; o >>= 1) {
        if (tid < o) red[tid] += red[tid + o];
        __syncthreads();
    }
    if (tid == 0) out[0] = red[0] / (float)BT_;
}

// ---------------- host orchestration ----------------
static inline void run_gemm(const float* A, const float* B, const float* bias,
                            float* C, int M, int N, int K, int relu) {
    dim3 grid((N + BN - 1) / BN, (M + BM - 1) / BM);
    gemm_bf16x3_kernel<<<grid, 256>>>(A, B, bias, C, M, N, K, relu);
}

extern "C" void kernel_launch(void* const* d_in, const int* in_sizes, int n_in,
                              void* d_out, int out_size) {
    const int*   index   = (const int*)  d_in[0];
    const int*   targets = (const int*)  d_in[1];
    const float* tok_emb = (const float*)d_in[2];
    const float* pos_emb = (const float*)d_in[3];
    const float* Wq      = (const float*)d_in[4];
    const float* Wk      = (const float*)d_in[5];
    const float* Wv      = (const float*)d_in[6];
    const float* Wo      = (const float*)d_in[7];
    const float* bo      = (const float*)d_in[8];
    const float* W1      = (const float*)d_in[9];
    const float* b1      = (const float*)d_in[10];
    const float* W2      = (const float*)d_in[11];
    const float* b2      = (const float*)d_in[12];
    const float* ln1_g   = (const float*)d_in[13];
    const float* ln1_b   = (const float*)d_in[14];
    const float* ln2_g   = (const float*)d_in[15];
    const float* ln2_b   = (const float*)d_in[16];
    const float* lnf_g   = (const float*)d_in[17];
    const float* lnf_b   = (const float*)d_in[18];
    const float* Wout    = (const float*)d_in[19];
    const float* bout    = (const float*)d_in[20];
    float* out = (float*)d_out;

    float *x, *qkv, *o, *y, *hid, *bpack;
    cudaGetSymbolAddress((void**)&x,     g_x);
    cudaGetSymbolAddress((void**)&qkv,   g_qkv);
    cudaGetSymbolAddress((void**)&o,     g_o);
    cudaGetSymbolAddress((void**)&y,     g_y);
    cudaGetSymbolAddress((void**)&hid,   g_hid);
    cudaGetSymbolAddress((void**)&bpack, g_Bpack);

    {
        int total = BT_ * D_;
        embed_kernel<<<(total + 255) / 256, 256>>>(index, tok_emb, pos_emb);
    }

    for (int l = 0; l < L_; l++) {
        {
            int total = D_ * 3 * D_;
            pack_qkv_kernel<<<(total + 255) / 256, 256>>>(Wq, Wk, Wv, l);
        }
        run_gemm(x, bpack, nullptr, qkv, BT_, 3 * D_, D_, 0);
        {
            dim3 grid(T_, B_ * H_);
            attn_kernel<<<grid, 128>>>();
        }
        run_gemm(o, Wo + (size_t)l * D_ * D_, bo + (size_t)l * D_, y, BT_, D_, D_, 0);
        add_ln_kernel<<<BT_, 128>>>(x, y, ln1_g + (size_t)l * D_, ln1_b + (size_t)l * D_, x);
        run_gemm(x, W1 + (size_t)l * D_ * FF_, b1 + (size_t)l * FF_, hid, BT_, FF_, D_, 1);
        run_gemm(hid, W2 + (size_t)l * FF_ * D_, b2 + (size_t)l * D_, y, BT_, D_, FF_, 0);
        add_ln_kernel<<<BT_, 128>>>(x, y, ln2_g + (size_t)l * D_, ln2_b + (size_t)l * D_, x);
    }

    add_ln_kernel<<<BT_, 128>>>(x, nullptr, lnf_g, lnf_b, o);

    const long long LOGITS = (long long)BT_ * V_;
    if ((long long)out_size >= LOGITS) {
        run_gemm(o, Wout, bout, out, BT_, V_, D_, 0);
        if ((long long)out_size > LOGITS) {
            row_loss_kernel<<<BT_, 256>>>(out, targets);
            reduce_loss_kernel<<<1, 256>>>(out + LOGITS);
        }
    } else {
        loss_direct_kernel<<<BT_, 256>>>(o, Wout, bout, targets);
        reduce_loss_kernel<<<1, 256>>>(out);
    }
}

// round 3
// speedup vs baseline: 1.5690x; 1.0769x over previous
#include <cuda_runtime.h>
#include <cuda_bf16.h>
#include <math.h>
#include <stdint.h>

// ---------------- problem constants ----------------
#define V_ 50257
#define VP_ 50304            // V padded to multiple of 128
#define D_ 384
#define T_ 300
#define B_ 16
#define H_ 16
#define DH_ 24
#define L_ 8
#define FF_ 1536
#define BT_ (B_ * T_)        // 4800
#define MP_ 4864             // BT padded to multiple of 128

// ---------------- scratch (device globals; no allocation allowed) ---------
__device__ float g_x[BT_ * D_];                 // residual stream fp32
__device__ float g_qkv[BT_ * 3 * D_];           // qkv output fp32
__device__ float g_y[BT_ * D_];                 // proj / mlp2 out fp32
__device__ float g_rowloss[BT_];

// activation bf16 planes (padded rows stay zero)
__device__ __nv_bfloat16 g_xh[MP_ * D_],  g_xl[MP_ * D_];
__device__ __nv_bfloat16 g_oh[MP_ * D_],  g_ol[MP_ * D_];
__device__ __nv_bfloat16 g_hh[MP_ * FF_], g_hl[MP_ * FF_];

// weight bf16 planes
__device__ __nv_bfloat16 g_wqkv_h[L_ * D_ * 3 * D_], g_wqkv_l[L_ * D_ * 3 * D_];
__device__ __nv_bfloat16 g_wo_h[L_ * D_ * D_],       g_wo_l[L_ * D_ * D_];
__device__ __nv_bfloat16 g_w1_h[L_ * D_ * FF_],      g_w1_l[L_ * D_ * FF_];
__device__ __nv_bfloat16 g_w2_h[L_ * FF_ * D_],      g_w2_l[L_ * FF_ * D_];
__device__ __nv_bfloat16 g_wout_h[D_ * VP_],         g_wout_l[D_ * VP_];

__device__ __forceinline__ void bf16_split(float x, __nv_bfloat16& h, __nv_bfloat16& l) {
    h = __float2bfloat16_rn(x);
    l = __float2bfloat16_rn(x - __bfloat162float(h));
}

// ---------------- weight conversions ----------------
__global__ void conv_split_kernel(const float* __restrict__ src,
                                  __nv_bfloat16* __restrict__ dh,
                                  __nv_bfloat16* __restrict__ dl, int n) {
    int i = blockIdx.x * blockDim.x + threadIdx.x;
    if (i >= n) return;
    bf16_split(src[i], dh[i], dl[i]);
}

__global__ void pack_qkv_bf16_kernel(const float* __restrict__ Wq,
                                     const float* __restrict__ Wk,
                                     const float* __restrict__ Wv) {
    int idx = blockIdx.x * blockDim.x + threadIdx.x;
    const int per_l = D_ * 3 * D_;
    if (idx >= L_ * per_l) return;
    int l = idx / per_l;
    int r = idx % per_l;
    int d = r / (3 * D_);
    int c = r % (3 * D_);
    int which = c / D_;
    int j = c % D_;
    int h = j / DH_;
    int e = j % DH_;
    const float* W = (which == 0) ? Wq : (which == 1) ? Wk : Wv;
    float v = W[(((size_t)l * H_ + h) * D_ + d) * DH_ + e];
    bf16_split(v, g_wqkv_h[idx], g_wqkv_l[idx]);
}

__global__ void conv_wout_kernel(const float* __restrict__ Wout) {
    int idx = blockIdx.x * blockDim.x + threadIdx.x;
    if (idx >= D_ * VP_) return;
    int k = idx / VP_;
    int n = idx % VP_;
    float v = (n < V_) ? Wout[(size_t)k * V_ + n] : 0.0f;
    bf16_split(v, g_wout_h[idx], g_wout_l[idx]);
}

// ---------------- embedding (fp32 + planes) ----------------
__global__ void embed_kernel(const int* __restrict__ index,
                             const float* __restrict__ tok_emb,
                             const float* __restrict__ pos_emb) {
    int i = blockIdx.x * blockDim.x + threadIdx.x;
    if (i >= BT_ * D_) return;
    int row = i / D_;
    int d   = i % D_;
    int t   = row % T_;
    float v = tok_emb[(size_t)index[row] * D_ + d] + pos_emb[t * D_ + d];
    g_x[i] = v;
    bf16_split(v, g_xh[i], g_xl[i]);
}

// ==================== bf16x3 tensor-core GEMM (pre-split operands) =======
// C[M,N] = A[M,K] @ B[K,N] (+bias, relu). A,B given as bf16 hi/lo planes.
// Block 128x128x32, 8 warps of 64x32, mma m16n8k16, register-prefetch pipeline.

#define BM 128
#define BN 128
#define A_PAD 40
#define B_PAD 136

__device__ __forceinline__ uint32_t smem_u32(const void* p) {
    return (uint32_t)__cvta_generic_to_shared(p);
}
__device__ __forceinline__ void ldm_x4(uint32_t* r, uint32_t addr) {
    asm volatile("ldmatrix.sync.aligned.m8n8.x4.shared.b16 {%0,%1,%2,%3}, [%4];"
                 : "=r"(r[0]), "=r"(r[1]), "=r"(r[2]), "=r"(r[3]) : "r"(addr));
}
__device__ __forceinline__ void ldm_x2_t(uint32_t* r, uint32_t addr) {
    asm volatile("ldmatrix.sync.aligned.m8n8.x2.trans.shared.b16 {%0,%1}, [%2];"
                 : "=r"(r[0]), "=r"(r[1]) : "r"(addr));
}
__device__ __forceinline__ void mma_bf16(float* d, const uint32_t* a, const uint32_t* b) {
    asm volatile("mma.sync.aligned.m16n8k16.row.col.f32.bf16.bf16.f32 "
                 "{%0,%1,%2,%3},{%4,%5,%6,%7},{%8,%9},{%0,%1,%2,%3};"
                 : "+f"(d[0]), "+f"(d[1]), "+f"(d[2]), "+f"(d[3])
                 : "r"(a[0]), "r"(a[1]), "r"(a[2]), "r"(a[3]), "r"(b[0]), "r"(b[1]));
}

__global__ __launch_bounds__(256)
void gemm_planes_kernel(const __nv_bfloat16* __restrict__ Ahg,
                        const __nv_bfloat16* __restrict__ Alg,
                        const __nv_bfloat16* __restrict__ Bhg,
                        const __nv_bfloat16* __restrict__ Blg,
                        const float* __restrict__ bias,
                        float* __restrict__ Cf,
                        __nv_bfloat16* __restrict__ Ch,
                        __nv_bfloat16* __restrict__ Cl,
                        int M, int N, int Npad, int K, int relu) {
    __shared__ __align__(16) __nv_bfloat16 Ah[BM][A_PAD];
    __shared__ __align__(16) __nv_bfloat16 Al[BM][A_PAD];
    __shared__ __align__(16) __nv_bfloat16 Bh[32][B_PAD];
    __shared__ __align__(16) __nv_bfloat16 Bl[32][B_PAD];

    const int tid = threadIdx.x;
    const int warp = tid >> 5;
    const int lane = tid & 31;
    const int wm = (warp >> 2) * 64;
    const int wn = (warp & 3) * 32;
    const int bm = blockIdx.y * BM;
    const int bn = blockIdx.x * BN;

    float acc[4][4][4];
#pragma unroll
    for (int i = 0; i < 4; i++)
#pragma unroll
        for (int j = 0; j < 4; j++)
#pragma unroll
            for (int f = 0; f < 4; f++) acc[i][j][f] = 0.0f;

    // tile-load lane mapping (uint4 = 8 bf16)
    const int a_r = tid >> 2;             // 0..63
    const int a_c = (tid & 3) * 8;        // 0,8,16,24
    const int b_r = tid >> 4;             // 0..15
    const int b_c = (tid & 15) * 8;       // 0..120

    const __nv_bfloat16* pAh = Ahg + (size_t)(bm + a_r) * K + a_c;
    const __nv_bfloat16* pAl = Alg + (size_t)(bm + a_r) * K + a_c;
    const __nv_bfloat16* pBh = Bhg + (size_t)b_r * Npad + bn + b_c;
    const __nv_bfloat16* pBl = Blg + (size_t)b_r * Npad + bn + b_c;
    const size_t aRowK = (size_t)64 * K;
    const size_t bRowN = (size_t)16 * Npad;

    // ldmatrix source coords
    const int f_row = (lane & 7) + ((lane >> 3) & 1) * 8;
    const int f_k8  = (lane >> 4) * 8;
    const int f_brow = lane & 15;

    uint4 ra0, ra1, ra2, ra3, rb0, rb1, rb2, rb3;
    // prefetch tile 0
    ra0 = *(const uint4*)(pAh);
    ra1 = *(const uint4*)(pAh + aRowK);
    ra2 = *(const uint4*)(pAl);
    ra3 = *(const uint4*)(pAl + aRowK);
    rb0 = *(const uint4*)(pBh);
    rb1 = *(const uint4*)(pBh + bRowN);
    rb2 = *(const uint4*)(pBl);
    rb3 = *(const uint4*)(pBl + bRowN);

    const int niter = K >> 5;
    for (int it = 0; it < niter; it++) {
        // commit prefetched tile to smem
        *(uint4*)&Ah[a_r][a_c]      = ra0;
        *(uint4*)&Ah[a_r + 64][a_c] = ra1;
        *(uint4*)&Al[a_r][a_c]      = ra2;
        *(uint4*)&Al[a_r + 64][a_c] = ra3;
        *(uint4*)&Bh[b_r][b_c]      = rb0;
        *(uint4*)&Bh[b_r + 16][b_c] = rb1;
        *(uint4*)&Bl[b_r][b_c]      = rb2;
        *(uint4*)&Bl[b_r + 16][b_c] = rb3;
        __syncthreads();

        // prefetch next tile while mma runs
        if (it + 1 < niter) {
            int k0 = (it + 1) << 5;
            ra0 = *(const uint4*)(pAh + k0);
            ra1 = *(const uint4*)(pAh + k0 + aRowK);
            ra2 = *(const uint4*)(pAl + k0);
            ra3 = *(const uint4*)(pAl + k0 + aRowK);
            rb0 = *(const uint4*)(pBh + (size_t)k0 * Npad);
            rb1 = *(const uint4*)(pBh + (size_t)k0 * Npad + bRowN);
            rb2 = *(const uint4*)(pBl + (size_t)k0 * Npad);
            rb3 = *(const uint4*)(pBl + (size_t)k0 * Npad + bRowN);
        }

#pragma unroll
        for (int ks = 0; ks < 2; ks++) {
            const int kk = ks * 16;
            uint32_t ah[4][4], al[4][4], bh[4][2], bl[4][2];
#pragma unroll
            for (int mt = 0; mt < 4; mt++) {
                int row = wm + mt * 16 + f_row;
                ldm_x4(ah[mt], smem_u32(&Ah[row][kk + f_k8]));
                ldm_x4(al[mt], smem_u32(&Al[row][kk + f_k8]));
            }
#pragma unroll
            for (int nt = 0; nt < 4; nt++) {
                int col = wn + nt * 8;
                ldm_x2_t(bh[nt], smem_u32(&Bh[kk + f_brow][col]));
                ldm_x2_t(bl[nt], smem_u32(&Bl[kk + f_brow][col]));
            }
#pragma unroll
            for (int mt = 0; mt < 4; mt++)
#pragma unroll
                for (int nt = 0; nt < 4; nt++) {
                    mma_bf16(acc[mt][nt], ah[mt], bh[nt]);
                    mma_bf16(acc[mt][nt], ah[mt], bl[nt]);
                    mma_bf16(acc[mt][nt], al[mt], bh[nt]);
                }
        }
        __syncthreads();
    }

    // ---- epilogue
    const int gid = lane >> 2;
    const int tig = lane & 3;
#pragma unroll
    for (int mt = 0; mt < 4; mt++) {
#pragma unroll
        for (int nt = 0; nt < 4; nt++) {
            int row0 = bm + wm + mt * 16 + gid;
            int col0 = bn + wn + nt * 8 + tig * 2;
#pragma unroll
            for (int f = 0; f < 4; f++) {
                int row = row0 + (f >> 1) * 8;
                int col = col0 + (f & 1);
                float v = acc[mt][nt][f];
                if (bias && col < N) v += bias[col];
                if (relu) v = fmaxf(v, 0.0f);
                if (Cf) {
                    if (row < M && col < N) Cf[(size_t)row * N + col] = v;
                } else {
                    // plane output: buffers padded, all rows/cols in-bounds
                    __nv_bfloat16 h, l;
                    bf16_split(v, h, l);
                    Ch[(size_t)row * Npad + col] = h;
                    Cl[(size_t)row * Npad + col] = l;
                }
            }
        }
    }
}

// ---------------- attention: one block per (tq, b*h) ----------------
__global__ __launch_bounds__(128)
void attn_kernel() {
    int tq = blockIdx.x;
    int bh = blockIdx.y;
    int b = bh / H_;
    int h = bh % H_;
    int tid = threadIdx.x;

    __shared__ float sc[T_];
    __shared__ float red[128];
    __shared__ float qs[DH_];
    __shared__ float oacc[128];

    const int base = (b * T_) * (3 * D_);
    if (tid < DH_) qs[tid] = g_qkv[(size_t)(b * T_ + tq) * (3 * D_) + h * DH_ + tid];
    __syncthreads();

    const float scale = rsqrtf((float)DH_);

    float lmax = -INFINITY;
    for (int ts = tid; ts <= tq; ts += 128) {
        const float* kp = &g_qkv[(size_t)base + (size_t)ts * (3 * D_) + D_ + h * DH_];
        float s = 0.0f;
#pragma unroll
        for (int e = 0; e < DH_; e++) s += qs[e] * kp[e];
        s *= scale;
        sc[ts] = s;
        lmax = fmaxf(lmax, s);
    }
    red[tid] = lmax;
    __syncthreads();
    for (int o = 64; o > 0; o >>= 1) {
        if (tid < o) red[tid] = fmaxf(red[tid], red[tid + o]);
        __syncthreads();
    }
    float m = red[0];
    __syncthreads();

    float lsum = 0.0f;
    for (int ts = tid; ts <= tq; ts += 128) {
        float p = __expf(sc[ts] - m);
        sc[ts] = p;
        lsum += p;
    }
    red[tid] = lsum;
    __syncthreads();
    for (int o = 64; o > 0; o >>= 1) {
        if (tid < o) red[tid] += red[tid + o];
        __syncthreads();
    }
    float inv = 1.0f / red[0];
    __syncthreads();

    float acc = 0.0f;
    if (tid < 120) {
        int e = tid % DH_;
        int r = tid / DH_;
        for (int ts = r; ts <= tq; ts += 5) {
            acc += sc[ts] * g_qkv[(size_t)base + (size_t)ts * (3 * D_) + 2 * D_ + h * DH_ + e];
        }
    }
    oacc[tid] = (tid < 120) ? acc : 0.0f;
    __syncthreads();
    if (tid < DH_) {
        float o = (oacc[tid] + oacc[tid + 24] + oacc[tid + 48] +
                   oacc[tid + 72] + oacc[tid + 96]) * inv;
        size_t idx = (size_t)(b * T_ + tq) * D_ + h * DH_ + tid;
        bf16_split(o, g_oh[idx], g_ol[idx]);
    }
}

// ---------------- fused residual-add + LayerNorm (+plane output) ---------
__global__ __launch_bounds__(128)
void add_ln_kernel(const float* __restrict__ x, const float* __restrict__ y,
                   const float* __restrict__ g, const float* __restrict__ bta,
                   float* __restrict__ outf, int write_planes) {
    int row = blockIdx.x;
    int tid = threadIdx.x;
    __shared__ float buf[D_];
    __shared__ float red[128];

    float s = 0.0f;
#pragma unroll
    for (int i = 0; i < D_ / 128; i++) {
        int d = tid + i * 128;
        float t = x[(size_t)row * D_ + d];
        if (y) t += y[(size_t)row * D_ + d];
        buf[d] = t;
        s += t;
    }
    red[tid] = s;
    __syncthreads();
    for (int o = 64; o > 0; o >>= 1) {
        if (tid < o) red[tid] += red[tid + o];
        __syncthreads();
    }
    float mean = red[0] / D_;
    __syncthreads();

    float s2 = 0.0f;
#pragma unroll
    for (int i = 0; i < D_ / 128; i++) {
        int d = tid + i * 128;
        float t = buf[d] - mean;
        s2 += t * t;
    }
    red[tid] = s2;
    __syncthreads();
    for (int o = 64; o > 0; o >>= 1) {
        if (tid < o) red[tid] += red[tid + o];
        __syncthreads();
    }
    float rstd = rsqrtf(red[0] / D_ + 1e-5f);
    __syncthreads();

#pragma unroll
    for (int i = 0; i < D_ / 128; i++) {
        int d = tid + i * 128;
        float v = (buf[d] - mean) * rstd * g[d] + bta[d];
        size_t idx = (size_t)row * D_ + d;
        if (outf) outf[idx] = v;
        if (write_planes) bf16_split(v, g_xh[idx], g_xl[idx]);
    }
}

// ---------------- loss ----------------
__global__ __launch_bounds__(256)
void row_loss_kernel(const float* __restrict__ logits, const int* __restrict__ targets) {
    int row = blockIdx.x;
    int tid = threadIdx.x;
    int tgt = targets[row];
    const float* lr = logits + (size_t)row * V_;

    __shared__ float sm[256], ss[256];
    __shared__ float szt;

    float m = -INFINITY, s = 0.0f, zt = 0.0f;
    for (int j = tid; j < V_; j += 256) {
        float z = lr[j];
        if (j == tgt) zt = z;
        float nm = fmaxf(m, z);
        s = s * __expf(m - nm) + __expf(z - nm);
        m = nm;
    }
    if ((tgt & 255) == tid) szt = zt;
    sm[tid] = m; ss[tid] = s;
    __syncthreads();
    for (int o = 128; o > 0; o >>= 1) {
        if (tid < o) {
            float m2 = sm[tid + o], s2 = ss[tid + o];
            float nm = fmaxf(sm[tid], m2);
            ss[tid] = ss[tid] * __expf(sm[tid] - nm) + s2 * __expf(m2 - nm);
            sm[tid] = nm;
        }
        __syncthreads();
    }
    if (tid == 0) g_rowloss[row] = (sm[0] + logf(ss[0])) - szt;
}

__global__ __launch_bounds__(256)
void loss_direct_kernel(const float* __restrict__ Wout, const float* __restrict__ bout,
                        const int* __restrict__ targets) {
    int row = blockIdx.x;
    int tid = threadIdx.x;
    int tgt = targets[row];
    __shared__ float xs[D_];
    __shared__ float sm[256], ss[256];
    __shared__ float szt;
    for (int i = tid; i < D_; i += 256)
        xs[i] = __bfloat162float(g_xh[(size_t)row * D_ + i]) +
                __bfloat162float(g_xl[(size_t)row * D_ + i]);
    __syncthreads();

    float m = -INFINITY, s = 0.0f, zt = 0.0f;
    for (int j = tid; j < V_; j += 256) {
        float z = bout[j];
        for (int k = 0; k < D_; k++) z += xs[k] * Wout[(size_t)k * V_ + j];
        if (j == tgt) zt = z;
        float nm = fmaxf(m, z);
        s = s * __expf(m - nm) + __expf(z - nm);
        m = nm;
    }
    if ((tgt & 255) == tid) szt = zt;
    sm[tid] = m; ss[tid] = s;
    __syncthreads();
    for (int o = 128; o > 0; o >>= 1) {
        if (tid < o) {
            float m2 = sm[tid + o], s2 = ss[tid + o];
            float nm = fmaxf(sm[tid], m2);
            ss[tid] = ss[tid] * __expf(sm[tid] - nm) + s2 * __expf(m2 - nm);
            sm[tid] = nm;
        }
        __syncthreads();
    }
    if (tid == 0) g_rowloss[row] = (sm[0] + logf(ss[0])) - szt;
}

__global__ __launch_bounds__(256)
void reduce_loss_kernel(float* __restrict__ out) {
    __shared__ float red[256];
    int tid = threadIdx.x;
    float s = 0.0f;
    for (int i = tid; i < BT_; i += 256) s += g_rowloss[i];
    red[tid] = s;
    __syncthreads();
    for (int o = 128; o > 0; o >>= 1) {
        if (tid < o) red[tid] += red[tid + o];
        __syncthreads();
    }
    if (tid == 0) out[0] = red[0] / (float)BT_;
}

// ---------------- host orchestration ----------------
extern "C" void kernel_launch(void* const* d_in, const int* in_sizes, int n_in,
                              void* d_out, int out_size) {
    const int*   index   = (const int*)  d_in[0];
    const int*   targets = (const int*)  d_in[1];
    const float* tok_emb = (const float*)d_in[2];
    const float* pos_emb = (const float*)d_in[3];
    const float* Wq      = (const float*)d_in[4];
    const float* Wk      = (const float*)d_in[5];
    const float* Wv      = (const float*)d_in[6];
    const float* Wo      = (const float*)d_in[7];
    const float* bo      = (const float*)d_in[8];
    const float* W1      = (const float*)d_in[9];
    const float* b1      = (const float*)d_in[10];
    const float* W2      = (const float*)d_in[11];
    const float* b2      = (const float*)d_in[12];
    const float* ln1_g   = (const float*)d_in[13];
    const float* ln1_b   = (const float*)d_in[14];
    const float* ln2_g   = (const float*)d_in[15];
    const float* ln2_b   = (const float*)d_in[16];
    const float* lnf_g   = (const float*)d_in[17];
    const float* lnf_b   = (const float*)d_in[18];
    const float* Wout    = (const float*)d_in[19];
    const float* bout    = (const float*)d_in[20];
    float* out = (float*)d_out;

    float *x, *qkv, *y;
    __nv_bfloat16 *xh, *xl, *oh, *ol, *hh, *hl;
    __nv_bfloat16 *wqkv_h, *wqkv_l, *wo_h, *wo_l, *w1_h, *w1_l, *w2_h, *w2_l, *wout_h, *wout_l;
    cudaGetSymbolAddress((void**)&x,   g_x);
    cudaGetSymbolAddress((void**)&qkv, g_qkv);
    cudaGetSymbolAddress((void**)&y,   g_y);
    cudaGetSymbolAddress((void**)&xh,  g_xh);   cudaGetSymbolAddress((void**)&xl, g_xl);
    cudaGetSymbolAddress((void**)&oh,  g_oh);   cudaGetSymbolAddress((void**)&ol, g_ol);
    cudaGetSymbolAddress((void**)&hh,  g_hh);   cudaGetSymbolAddress((void**)&hl, g_hl);
    cudaGetSymbolAddress((void**)&wqkv_h, g_wqkv_h); cudaGetSymbolAddress((void**)&wqkv_l, g_wqkv_l);
    cudaGetSymbolAddress((void**)&wo_h,   g_wo_h);   cudaGetSymbolAddress((void**)&wo_l,   g_wo_l);
    cudaGetSymbolAddress((void**)&w1_h,   g_w1_h);   cudaGetSymbolAddress((void**)&w1_l,   g_w1_l);
    cudaGetSymbolAddress((void**)&w2_h,   g_w2_h);   cudaGetSymbolAddress((void**)&w2_l,   g_w2_l);
    cudaGetSymbolAddress((void**)&wout_h, g_wout_h); cudaGetSymbolAddress((void**)&wout_l, g_wout_l);

    // ---- weight conversions (per call; constant results)
    {
        int n = L_ * D_ * 3 * D_;
        pack_qkv_bf16_kernel<<<(n + 255) / 256, 256>>>(Wq, Wk, Wv);
        n = L_ * D_ * D_;
        conv_split_kernel<<<(n + 255) / 256, 256>>>(Wo, wo_h, wo_l, n);
        n = L_ * D_ * FF_;
        conv_split_kernel<<<(n + 255) / 256, 256>>>(W1, w1_h, w1_l, n);
        conv_split_kernel<<<(n + 255) / 256, 256>>>(W2, w2_h, w2_l, n);
        n = D_ * VP_;
        conv_wout_kernel<<<(n + 255) / 256, 256>>>(Wout);
    }

    // ---- embedding
    {
        int total = BT_ * D_;
        embed_kernel<<<(total + 255) / 256, 256>>>(index, tok_emb, pos_emb);
    }

    const dim3 blk(256);
    // ---- transformer layers
    for (int l = 0; l < L_; l++) {
        // qkv = x @ Wqkv  [MP,384]x[384,1152] -> fp32
        gemm_planes_kernel<<<dim3(1152 / BN, MP_ / BM), blk>>>(
            xh, xl, wqkv_h + (size_t)l * D_ * 3 * D_, wqkv_l + (size_t)l * D_ * 3 * D_,
            nullptr, qkv, nullptr, nullptr, BT_, 3 * D_, 3 * D_, D_, 0);
        // attention -> o planes
        attn_kernel<<<dim3(T_, B_ * H_), 128>>>();
        // y = o @ Wo + bo -> fp32
        gemm_planes_kernel<<<dim3(D_ / BN, MP_ / BM), blk>>>(
            oh, ol, wo_h + (size_t)l * D_ * D_, wo_l + (size_t)l * D_ * D_,
            bo + (size_t)l * D_, y, nullptr, nullptr, BT_, D_, D_, D_, 0);
        // x = LN(x + y) -> fp32 + planes
        add_ln_kernel<<<BT_, 128>>>(x, y, ln1_g + (size_t)l * D_, ln1_b + (size_t)l * D_, x, 1);
        // hid = relu(x @ W1 + b1) -> planes only
        gemm_planes_kernel<<<dim3(FF_ / BN, MP_ / BM), blk>>>(
            xh, xl, w1_h + (size_t)l * D_ * FF_, w1_l + (size_t)l * D_ * FF_,
            b1 + (size_t)l * FF_, nullptr, hh, hl, BT_, FF_, FF_, D_, 1);
        // y = hid @ W2 + b2 -> fp32
        gemm_planes_kernel<<<dim3(D_ / BN, MP_ / BM), blk>>>(
            hh, hl, w2_h + (size_t)l * FF_ * D_, w2_l + (size_t)l * FF_ * D_,
            b2 + (size_t)l * D_, y, nullptr, nullptr, BT_, D_, D_, FF_, 0);
        // x = LN(x + y) -> fp32 + planes
        add_ln_kernel<<<BT_, 128>>>(x, y, ln2_g + (size_t)l * D_, ln2_b + (size_t)l * D_, x, 1);
    }

    // ---- final LN -> planes only (xh/xl reused)
    add_ln_kernel<<<BT_, 128>>>(x, nullptr, lnf_g, lnf_b, nullptr, 1);

    const long long LOGITS = (long long)BT_ * V_;
    if ((long long)out_size >= LOGITS) {
        // logits = xf @ Wout + bout -> d_out
        gemm_planes_kernel<<<dim3(VP_ / BN, MP_ / BM), blk>>>(
            xh, xl, wout_h, wout_l, bout, out, nullptr, nullptr, BT_, V_, VP_, D_, 0);
        if ((long long)out_size > LOGITS) {
            row_loss_kernel<<<BT_, 256>>>(out, targets);
            reduce_loss_kernel<<<1, 256>>>(out + LOGITS);
        }
    } else {
        loss_direct_kernel<<<BT_, 256>>>(Wout, bout, targets);
        reduce_loss_kernel<<<1, 256>>>(out);
    }
}

// round 4
// speedup vs baseline: 1.6055x; 1.0232x over previous
#include <cuda_runtime.h>
#include <cuda_bf16.h>
#include <math.h>
#include <stdint.h>

// ---------------- problem constants ----------------
#define V_ 50257
#define VP_ 50304            // V padded to multiple of 128
#define D_ 384
#define T_ 300
#define B_ 16
#define H_ 16
#define DH_ 24
#define L_ 8
#define FF_ 1536
#define BT_ (B_ * T_)        // 4800
#define MP_ 4864             // BT padded to multiple of 128

// ---------------- scratch (device globals; no allocation allowed) ---------
__device__ float g_x[BT_ * D_];
__device__ float g_qkv[BT_ * 3 * D_];
__device__ float g_y[BT_ * D_];
__device__ float g_rowloss[BT_];

__device__ __nv_bfloat16 g_xh[MP_ * D_],  g_xl[MP_ * D_];
__device__ __nv_bfloat16 g_oh[MP_ * D_],  g_ol[MP_ * D_];
__device__ __nv_bfloat16 g_hh[MP_ * FF_], g_hl[MP_ * FF_];

__device__ __nv_bfloat16 g_wqkv_h[L_ * D_ * 3 * D_], g_wqkv_l[L_ * D_ * 3 * D_];
__device__ __nv_bfloat16 g_wo_h[L_ * D_ * D_],       g_wo_l[L_ * D_ * D_];
__device__ __nv_bfloat16 g_w1_h[L_ * D_ * FF_],      g_w1_l[L_ * D_ * FF_];
__device__ __nv_bfloat16 g_w2_h[L_ * FF_ * D_],      g_w2_l[L_ * FF_ * D_];
__device__ __nv_bfloat16 g_wout_h[D_ * VP_],         g_wout_l[D_ * VP_];

__device__ __forceinline__ void bf16_split(float x, __nv_bfloat16& h, __nv_bfloat16& l) {
    h = __float2bfloat16_rn(x);
    l = __float2bfloat16_rn(x - __bfloat162float(h));
}

// ---------------- weight conversions ----------------
__global__ void conv_split_kernel(const float* __restrict__ src,
                                  __nv_bfloat16* __restrict__ dh,
                                  __nv_bfloat16* __restrict__ dl, int n) {
    int i = blockIdx.x * blockDim.x + threadIdx.x;
    if (i >= n) return;
    bf16_split(src[i], dh[i], dl[i]);
}

__global__ void pack_qkv_bf16_kernel(const float* __restrict__ Wq,
                                     const float* __restrict__ Wk,
                                     const float* __restrict__ Wv) {
    int idx = blockIdx.x * blockDim.x + threadIdx.x;
    const int per_l = D_ * 3 * D_;
    if (idx >= L_ * per_l) return;
    int l = idx / per_l;
    int r = idx % per_l;
    int d = r / (3 * D_);
    int c = r % (3 * D_);
    int which = c / D_;
    int j = c % D_;
    int h = j / DH_;
    int e = j % DH_;
    const float* W = (which == 0) ? Wq : (which == 1) ? Wk : Wv;
    float v = W[(((size_t)l * H_ + h) * D_ + d) * DH_ + e];
    bf16_split(v, g_wqkv_h[idx], g_wqkv_l[idx]);
}

__global__ void conv_wout_kernel(const float* __restrict__ Wout) {
    int idx = blockIdx.x * blockDim.x + threadIdx.x;
    if (idx >= D_ * VP_) return;
    int k = idx / VP_;
    int n = idx % VP_;
    float v = (n < V_) ? Wout[(size_t)k * V_ + n] : 0.0f;
    bf16_split(v, g_wout_h[idx], g_wout_l[idx]);
}

// ---------------- embedding ----------------
__global__ void embed_kernel(const int* __restrict__ index,
                             const float* __restrict__ tok_emb,
                             const float* __restrict__ pos_emb) {
    int i = blockIdx.x * blockDim.x + threadIdx.x;
    if (i >= BT_ * D_) return;
    int row = i / D_;
    int d   = i % D_;
    int t   = row % T_;
    float v = tok_emb[(size_t)index[row] * D_ + d] + pos_emb[t * D_ + d];
    g_x[i] = v;
    bf16_split(v, g_xh[i], g_xl[i]);
}

// ==================== bf16x3 GEMM, cp.async 2-stage pipeline ==============
#define BN 128
#define A_PAD 40
#define B_PAD 136

__device__ __forceinline__ uint32_t smem_u32(const void* p) {
    return (uint32_t)__cvta_generic_to_shared(p);
}
__device__ __forceinline__ void cp16(void* sp, const void* gp) {
    asm volatile("cp.async.cg.shared.global [%0], [%1], 16;"
                 :: "r"(smem_u32(sp)), "l"(gp));
}
__device__ __forceinline__ void cp_commit() {
    asm volatile("cp.async.commit_group;");
}
__device__ __forceinline__ void cp_wait1() {
    asm volatile("cp.async.wait_group 1;");
}
__device__ __forceinline__ void ldm_x4(uint32_t* r, uint32_t addr) {
    asm volatile("ldmatrix.sync.aligned.m8n8.x4.shared.b16 {%0,%1,%2,%3}, [%4];"
                 : "=r"(r[0]), "=r"(r[1]), "=r"(r[2]), "=r"(r[3]) : "r"(addr));
}
__device__ __forceinline__ void ldm_x2_t(uint32_t* r, uint32_t addr) {
    asm volatile("ldmatrix.sync.aligned.m8n8.x2.trans.shared.b16 {%0,%1}, [%2];"
                 : "=r"(r[0]), "=r"(r[1]) : "r"(addr));
}
__device__ __forceinline__ void mma_bf16(float* d, const uint32_t* a, const uint32_t* b) {
    asm volatile("mma.sync.aligned.m16n8k16.row.col.f32.bf16.bf16.f32 "
                 "{%0,%1,%2,%3},{%4,%5,%6,%7},{%8,%9},{%0,%1,%2,%3};"
                 : "+f"(d[0]), "+f"(d[1]), "+f"(d[2]), "+f"(d[3])
                 : "r"(a[0]), "r"(a[1]), "r"(a[2]), "r"(a[3]), "r"(b[0]), "r"(b[1]));
}

// MT: number of 16-row m-tiles per warp. BM = 32*MT (128 or 64).
template <int MT>
__global__ __launch_bounds__(256, 2)
void gemm_pipe_kernel(const __nv_bfloat16* __restrict__ Ahg,
                      const __nv_bfloat16* __restrict__ Alg,
                      const __nv_bfloat16* __restrict__ Bhg,
                      const __nv_bfloat16* __restrict__ Blg,
                      const float* __restrict__ bias,
                      float* __restrict__ Cf,
                      __nv_bfloat16* __restrict__ Ch,
                      __nv_bfloat16* __restrict__ Cl,
                      int M, int N, int Npad, int K, int relu) {
    constexpr int BM = 32 * MT;
    constexpr int A_STAGE = BM * A_PAD;   // elems per A plane-stage
    constexpr int B_STAGE = 32 * B_PAD;
    extern __shared__ __nv_bfloat16 sm[];
    // layout: Ah[2], Al[2], Bh[2], Bl[2]
    __nv_bfloat16* sAh = sm;
    __nv_bfloat16* sAl = sAh + 2 * A_STAGE;
    __nv_bfloat16* sBh = sAl + 2 * A_STAGE;
    __nv_bfloat16* sBl = sBh + 2 * B_STAGE;

    const int tid = threadIdx.x;
    const int warp = tid >> 5;
    const int lane = tid & 31;
    const int wm = (warp >> 2) * (16 * MT);
    const int wn = (warp & 3) * 32;
    const int bm = blockIdx.y * BM;
    const int bn = blockIdx.x * BN;

    float acc[MT][4][4];
#pragma unroll
    for (int i = 0; i < MT; i++)
#pragma unroll
        for (int j = 0; j < 4; j++)
#pragma unroll
            for (int f = 0; f < 4; f++) acc[i][j][f] = 0.0f;

    // load mapping (16B = 8 bf16 per cp.async)
    const int a_r = tid >> 2;             // 0..63
    const int a_c = (tid & 3) * 8;        // 0,8,16,24
    const int b_r = tid >> 4;             // 0..15
    const int b_c = (tid & 15) * 8;       // 0..120

    const __nv_bfloat16* pAh = Ahg + (size_t)(bm + a_r) * K + a_c;
    const __nv_bfloat16* pAl = Alg + (size_t)(bm + a_r) * K + a_c;
    const __nv_bfloat16* pBh = Bhg + (size_t)b_r * Npad + bn + b_c;
    const __nv_bfloat16* pBl = Blg + (size_t)b_r * Npad + bn + b_c;
    const size_t aRowK = (size_t)64 * K;
    const size_t bRowN = (size_t)16 * Npad;

    const int niter = K >> 5;

    auto load_stage = [&](int it, int s) {
        const int k0 = it << 5;
        __nv_bfloat16* ah = sAh + s * A_STAGE;
        __nv_bfloat16* al = sAl + s * A_STAGE;
        __nv_bfloat16* bh = sBh + s * B_STAGE;
        __nv_bfloat16* bl = sBl + s * B_STAGE;
#pragma unroll
        for (int g = 0; g < BM / 64; g++) {
            cp16(&ah[(a_r + g * 64) * A_PAD + a_c], pAh + k0 + g * aRowK);
            cp16(&al[(a_r + g * 64) * A_PAD + a_c], pAl + k0 + g * aRowK);
        }
        cp16(&bh[b_r * B_PAD + b_c],        pBh + (size_t)k0 * Npad);
        cp16(&bh[(b_r + 16) * B_PAD + b_c], pBh + (size_t)k0 * Npad + bRowN);
        cp16(&bl[b_r * B_PAD + b_c],        pBl + (size_t)k0 * Npad);
        cp16(&bl[(b_r + 16) * B_PAD + b_c], pBl + (size_t)k0 * Npad + bRowN);
    };

    // ldmatrix lane coords
    const int f_row = (lane & 7) + ((lane >> 3) & 1) * 8;
    const int f_k8  = (lane >> 4) * 8;
    const int f_brow = lane & 15;

    load_stage(0, 0);
    cp_commit();

    for (int it = 0; it < niter; it++) {
        if (it + 1 < niter) load_stage(it + 1, (it + 1) & 1);
        cp_commit();
        cp_wait1();
        __syncthreads();

        const int s = it & 1;
        const __nv_bfloat16* ahs = sAh + s * A_STAGE;
        const __nv_bfloat16* als = sAl + s * A_STAGE;
        const __nv_bfloat16* bhs = sBh + s * B_STAGE;
        const __nv_bfloat16* bls = sBl + s * B_STAGE;

#pragma unroll
        for (int ks = 0; ks < 2; ks++) {
            const int kk = ks * 16;
            uint32_t ah[MT][4], al[MT][4], bh[4][2], bl[4][2];
#pragma unroll
            for (int mt = 0; mt < MT; mt++) {
                int row = wm + mt * 16 + f_row;
                ldm_x4(ah[mt], smem_u32(&ahs[row * A_PAD + kk + f_k8]));
                ldm_x4(al[mt], smem_u32(&als[row * A_PAD + kk + f_k8]));
            }
#pragma unroll
            for (int nt = 0; nt < 4; nt++) {
                int col = wn + nt * 8;
                ldm_x2_t(bh[nt], smem_u32(&bhs[(kk + f_brow) * B_PAD + col]));
                ldm_x2_t(bl[nt], smem_u32(&bls[(kk + f_brow) * B_PAD + col]));
            }
#pragma unroll
            for (int mt = 0; mt < MT; mt++)
#pragma unroll
                for (int nt = 0; nt < 4; nt++) {
                    mma_bf16(acc[mt][nt], ah[mt], bh[nt]);
                    mma_bf16(acc[mt][nt], ah[mt], bl[nt]);
                    mma_bf16(acc[mt][nt], al[mt], bh[nt]);
                }
        }
        __syncthreads();
    }

    // ---- epilogue
    const int gid = lane >> 2;
    const int tig = lane & 3;
#pragma unroll
    for (int mt = 0; mt < MT; mt++) {
#pragma unroll
        for (int nt = 0; nt < 4; nt++) {
            int row0 = bm + wm + mt * 16 + gid;
            int col0 = bn + wn + nt * 8 + tig * 2;
#pragma unroll
            for (int f = 0; f < 4; f++) {
                int row = row0 + (f >> 1) * 8;
                int col = col0 + (f & 1);
                float v = acc[mt][nt][f];
                if (bias && col < N) v += bias[col];
                if (relu) v = fmaxf(v, 0.0f);
                if (Cf) {
                    if (row < M && col < N) Cf[(size_t)row * N + col] = v;
                } else {
                    __nv_bfloat16 h, l;
                    bf16_split(v, h, l);
                    Ch[(size_t)row * Npad + col] = h;
                    Cl[(size_t)row * Npad + col] = l;
                }
            }
        }
    }
}

// ---------------- attention ----------------
__global__ __launch_bounds__(128)
void attn_kernel() {
    int tq = blockIdx.x;
    int bh = blockIdx.y;
    int b = bh / H_;
    int h = bh % H_;
    int tid = threadIdx.x;

    __shared__ float sc[T_];
    __shared__ float red[128];
    __shared__ float qs[DH_];
    __shared__ float oacc[128];

    const int base = (b * T_) * (3 * D_);
    if (tid < DH_) qs[tid] = g_qkv[(size_t)(b * T_ + tq) * (3 * D_) + h * DH_ + tid];
    __syncthreads();

    const float scale = rsqrtf((float)DH_);

    float lmax = -INFINITY;
    for (int ts = tid; ts <= tq; ts += 128) {
        const float* kp = &g_qkv[(size_t)base + (size_t)ts * (3 * D_) + D_ + h * DH_];
        float s = 0.0f;
#pragma unroll
        for (int e = 0; e < DH_; e++) s += qs[e] * kp[e];
        s *= scale;
        sc[ts] = s;
        lmax = fmaxf(lmax, s);
    }
    red[tid] = lmax;
    __syncthreads();
    for (int o = 64; o > 0; o >>= 1) {
        if (tid < o) red[tid] = fmaxf(red[tid], red[tid + o]);
        __syncthreads();
    }
    float m = red[0];
    __syncthreads();

    float lsum = 0.0f;
    for (int ts = tid; ts <= tq; ts += 128) {
        float p = __expf(sc[ts] - m);
        sc[ts] = p;
        lsum += p;
    }
    red[tid] = lsum;
    __syncthreads();
    for (int o = 64; o > 0; o >>= 1) {
        if (tid < o) red[tid] += red[tid + o];
        __syncthreads();
    }
    float inv = 1.0f / red[0];
    __syncthreads();

    float acc = 0.0f;
    if (tid < 120) {
        int e = tid % DH_;
        int r = tid / DH_;
        for (int ts = r; ts <= tq; ts += 5) {
            acc += sc[ts] * g_qkv[(size_t)base + (size_t)ts * (3 * D_) + 2 * D_ + h * DH_ + e];
        }
    }
    oacc[tid] = (tid < 120) ? acc : 0.0f;
    __syncthreads();
    if (tid < DH_) {
        float o = (oacc[tid] + oacc[tid + 24] + oacc[tid + 48] +
                   oacc[tid + 72] + oacc[tid + 96]) * inv;
        size_t idx = (size_t)(b * T_ + tq) * D_ + h * DH_ + tid;
        bf16_split(o, g_oh[idx], g_ol[idx]);
    }
}

// ---------------- fused residual-add + LayerNorm ----------------
__global__ __launch_bounds__(128)
void add_ln_kernel(const float* __restrict__ x, const float* __restrict__ y,
                   const float* __restrict__ g, const float* __restrict__ bta,
                   float* __restrict__ outf, int write_planes) {
    int row = blockIdx.x;
    int tid = threadIdx.x;
    __shared__ float buf[D_];
    __shared__ float red[128];

    float s = 0.0f;
#pragma unroll
    for (int i = 0; i < D_ / 128; i++) {
        int d = tid + i * 128;
        float t = x[(size_t)row * D_ + d];
        if (y) t += y[(size_t)row * D_ + d];
        buf[d] = t;
        s += t;
    }
    red[tid] = s;
    __syncthreads();
    for (int o = 64; o > 0; o >>= 1) {
        if (tid < o) red[tid] += red[tid + o];
        __syncthreads();
    }
    float mean = red[0] / D_;
    __syncthreads();

    float s2 = 0.0f;
#pragma unroll
    for (int i = 0; i < D_ / 128; i++) {
        int d = tid + i * 128;
        float t = buf[d] - mean;
        s2 += t * t;
    }
    red[tid] = s2;
    __syncthreads();
    for (int o = 64; o > 0; o >>= 1) {
        if (tid < o) red[tid] += red[tid + o];
        __syncthreads();
    }
    float rstd = rsqrtf(red[0] / D_ + 1e-5f);
    __syncthreads();

#pragma unroll
    for (int i = 0; i < D_ / 128; i++) {
        int d = tid + i * 128;
        float v = (buf[d] - mean) * rstd * g[d] + bta[d];
        size_t idx = (size_t)row * D_ + d;
        if (outf) outf[idx] = v;
        if (write_planes) bf16_split(v, g_xh[idx], g_xl[idx]);
    }
}

// ---------------- loss ----------------
__global__ __launch_bounds__(256)
void row_loss_kernel(const float* __restrict__ logits, const int* __restrict__ targets) {
    int row = blockIdx.x;
    int tid = threadIdx.x;
    int tgt = targets[row];
    const float* lr = logits + (size_t)row * V_;

    __shared__ float sm[256], ss[256];
    __shared__ float szt;

    float m = -INFINITY, s = 0.0f, zt = 0.0f;
    for (int j = tid; j < V_; j += 256) {
        float z = lr[j];
        if (j == tgt) zt = z;
        float nm = fmaxf(m, z);
        s = s * __expf(m - nm) + __expf(z - nm);
        m = nm;
    }
    if ((tgt & 255) == tid) szt = zt;
    sm[tid] = m; ss[tid] = s;
    __syncthreads();
    for (int o = 128; o > 0; o >>= 1) {
        if (tid < o) {
            float m2 = sm[tid + o], s2 = ss[tid + o];
            float nm = fmaxf(sm[tid], m2);
            ss[tid] = ss[tid] * __expf(sm[tid] - nm) + s2 * __expf(m2 - nm);
            sm[tid] = nm;
        }
        __syncthreads();
    }
    if (tid == 0) g_rowloss[row] = (sm[0] + logf(ss[0])) - szt;
}

__global__ __launch_bounds__(256)
void loss_direct_kernel(const float* __restrict__ Wout, const float* __restrict__ bout,
                        const int* __restrict__ targets) {
    int row = blockIdx.x;
    int tid = threadIdx.x;
    int tgt = targets[row];
    __shared__ float xs[D_];
    __shared__ float sm[256], ss[256];
    __shared__ float szt;
    for (int i = tid; i < D_; i += 256)
        xs[i] = __bfloat162float(g_xh[(size_t)row * D_ + i]) +
                __bfloat162float(g_xl[(size_t)row * D_ + i]);
    __syncthreads();

    float m = -INFINITY, s = 0.0f, zt = 0.0f;
    for (int j = tid; j < V_; j += 256) {
        float z = bout[j];
        for (int k = 0; k < D_; k++) z += xs[k] * Wout[(size_t)k * V_ + j];
        if (j == tgt) zt = z;
        float nm = fmaxf(m, z);
        s = s * __expf(m - nm) + __expf(z - nm);
        m = nm;
    }
    if ((tgt & 255) == tid) szt = zt;
    sm[tid] = m; ss[tid] = s;
    __syncthreads();
    for (int o = 128; o > 0; o >>= 1) {
        if (tid < o) {
            float m2 = sm[tid + o], s2 = ss[tid + o];
            float nm = fmaxf(sm[tid], m2);
            ss[tid] = ss[tid] * __expf(sm[tid] - nm) + s2 * __expf(m2 - nm);
            sm[tid] = nm;
        }
        __syncthreads();
    }
    if (tid == 0) g_rowloss[row] = (sm[0] + logf(ss[0])) - szt;
}

__global__ __launch_bounds__(256)
void reduce_loss_kernel(float* __restrict__ out) {
    __shared__ float red[256];
    int tid = threadIdx.x;
    float s = 0.0f;
    for (int i = tid; i < BT_; i += 256) s += g_rowloss[i];
    red[tid] = s;
    __syncthreads();
    for (int o = 128; o > 0; o >>= 1) {
        if (tid < o) red[tid] += red[tid + o];
        __syncthreads();
    }
    if (tid == 0) out[0] = red[0] / (float)BT_;
}

// ---------------- host orchestration ----------------
#define SMEM_MT4 ((2 * 2 * 128 * A_PAD + 2 * 2 * 32 * B_PAD) * (int)sizeof(__nv_bfloat16))
#define SMEM_MT2 ((2 * 2 * 64  * A_PAD + 2 * 2 * 32 * B_PAD) * (int)sizeof(__nv_bfloat16))

extern "C" void kernel_launch(void* const* d_in, const int* in_sizes, int n_in,
                              void* d_out, int out_size) {
    const int*   index   = (const int*)  d_in[0];
    const int*   targets = (const int*)  d_in[1];
    const float* tok_emb = (const float*)d_in[2];
    const float* pos_emb = (const float*)d_in[3];
    const float* Wq      = (const float*)d_in[4];
    const float* Wk      = (const float*)d_in[5];
    const float* Wv      = (const float*)d_in[6];
    const float* Wo      = (const float*)d_in[7];
    const float* bo      = (const float*)d_in[8];
    const float* W1      = (const float*)d_in[9];
    const float* b1      = (const float*)d_in[10];
    const float* W2      = (const float*)d_in[11];
    const float* b2      = (const float*)d_in[12];
    const float* ln1_g   = (const float*)d_in[13];
    const float* ln1_b   = (const float*)d_in[14];
    const float* ln2_g   = (const float*)d_in[15];
    const float* ln2_b   = (const float*)d_in[16];
    const float* lnf_g   = (const float*)d_in[17];
    const float* lnf_b   = (const float*)d_in[18];
    const float* Wout    = (const float*)d_in[19];
    const float* bout    = (const float*)d_in[20];
    float* out = (float*)d_out;

    float *x, *qkv, *y;
    __nv_bfloat16 *xh, *xl, *oh, *ol, *hh, *hl;
    __nv_bfloat16 *wqkv_h, *wqkv_l, *wo_h, *wo_l, *w1_h, *w1_l, *w2_h, *w2_l, *wout_h, *wout_l;
    cudaGetSymbolAddress((void**)&x,   g_x);
    cudaGetSymbolAddress((void**)&qkv, g_qkv);
    cudaGetSymbolAddress((void**)&y,   g_y);
    cudaGetSymbolAddress((void**)&xh,  g_xh);   cudaGetSymbolAddress((void**)&xl, g_xl);
    cudaGetSymbolAddress((void**)&oh,  g_oh);   cudaGetSymbolAddress((void**)&ol, g_ol);
    cudaGetSymbolAddress((void**)&hh,  g_hh);   cudaGetSymbolAddress((void**)&hl, g_hl);
    cudaGetSymbolAddress((void**)&wqkv_h, g_wqkv_h); cudaGetSymbolAddress((void**)&wqkv_l, g_wqkv_l);
    cudaGetSymbolAddress((void**)&wo_h,   g_wo_h);   cudaGetSymbolAddress((void**)&wo_l,   g_wo_l);
    cudaGetSymbolAddress((void**)&w1_h,   g_w1_h);   cudaGetSymbolAddress((void**)&w1_l,   g_w1_l);
    cudaGetSymbolAddress((void**)&w2_h,   g_w2_h);   cudaGetSymbolAddress((void**)&w2_l,   g_w2_l);
    cudaGetSymbolAddress((void**)&wout_h, g_wout_h); cudaGetSymbolAddress((void**)&wout_l, g_wout_l);

    cudaFuncSetAttribute(gemm_pipe_kernel<4>, cudaFuncAttributeMaxDynamicSharedMemorySize, SMEM_MT4);
    cudaFuncSetAttribute(gemm_pipe_kernel<2>, cudaFuncAttributeMaxDynamicSharedMemorySize, SMEM_MT2);

    // ---- weight conversions
    {
        int n = L_ * D_ * 3 * D_;
        pack_qkv_bf16_kernel<<<(n + 255) / 256, 256>>>(Wq, Wk, Wv);
        n = L_ * D_ * D_;
        conv_split_kernel<<<(n + 255) / 256, 256>>>(Wo, wo_h, wo_l, n);
        n = L_ * D_ * FF_;
        conv_split_kernel<<<(n + 255) / 256, 256>>>(W1, w1_h, w1_l, n);
        conv_split_kernel<<<(n + 255) / 256, 256>>>(W2, w2_h, w2_l, n);
        n = D_ * VP_;
        conv_wout_kernel<<<(n + 255) / 256, 256>>>(Wout);
    }

    // ---- embedding
    {
        int total = BT_ * D_;
        embed_kernel<<<(total + 255) / 256, 256>>>(index, tok_emb, pos_emb);
    }

    const dim3 blk(256);
    for (int l = 0; l < L_; l++) {
        // qkv = x @ Wqkv -> fp32
        gemm_pipe_kernel<4><<<dim3(1152 / BN, MP_ / 128), blk, SMEM_MT4>>>(
            xh, xl, wqkv_h + (size_t)l * D_ * 3 * D_, wqkv_l + (size_t)l * D_ * 3 * D_,
            nullptr, qkv, nullptr, nullptr, BT_, 3 * D_, 3 * D_, D_, 0);
        attn_kernel<<<dim3(T_, B_ * H_), 128>>>();
        // y = o @ Wo + bo -> fp32 (N=384: MT=2 for grid fill)
        gemm_pipe_kernel<2><<<dim3(D_ / BN, MP_ / 64), blk, SMEM_MT2>>>(
            oh, ol, wo_h + (size_t)l * D_ * D_, wo_l + (size_t)l * D_ * D_,
            bo + (size_t)l * D_, y, nullptr, nullptr, BT_, D_, D_, D_, 0);
        add_ln_kernel<<<BT_, 128>>>(x, y, ln1_g + (size_t)l * D_, ln1_b + (size_t)l * D_, x, 1);
        // hid = relu(x @ W1 + b1) -> planes
        gemm_pipe_kernel<4><<<dim3(FF_ / BN, MP_ / 128), blk, SMEM_MT4>>>(
            xh, xl, w1_h + (size_t)l * D_ * FF_, w1_l + (size_t)l * D_ * FF_,
            b1 + (size_t)l * FF_, nullptr, hh, hl, BT_, FF_, FF_, D_, 1);
        // y = hid @ W2 + b2 -> fp32 (N=384: MT=2)
        gemm_pipe_kernel<2><<<dim3(D_ / BN, MP_ / 64), blk, SMEM_MT2>>>(
            hh, hl, w2_h + (size_t)l * FF_ * D_, w2_l + (size_t)l * FF_ * D_,
            b2 + (size_t)l * D_, y, nullptr, nullptr, BT_, D_, D_, FF_, 0);
        add_ln_kernel<<<BT_, 128>>>(x, y, ln2_g + (size_t)l * D_, ln2_b + (size_t)l * D_, x, 1);
    }

    add_ln_kernel<<<BT_, 128>>>(x, nullptr, lnf_g, lnf_b, nullptr, 1);

    const long long LOGITS = (long long)BT_ * V_;
    if ((long long)out_size >= LOGITS) {
        gemm_pipe_kernel<4><<<dim3(VP_ / BN, MP_ / 128), blk, SMEM_MT4>>>(
            xh, xl, wout_h, wout_l, bout, out, nullptr, nullptr, BT_, V_, VP_, D_, 0);
        if ((long long)out_size > LOGITS) {
            row_loss_kernel<<<BT_, 256>>>(out, targets);
            reduce_loss_kernel<<<1, 256>>>(out + LOGITS);
        }
    } else {
        loss_direct_kernel<<<BT_, 256>>>(Wout, bout, targets);
        reduce_loss_kernel<<<1, 256>>>(out);
    }
}